// round 16
// baseline (speedup 1.0000x reference)
#include <cuda_runtime.h>
#include <cuda_fp16.h>
#include <mma.h>
#include <math.h>

using namespace nvcuda;

#define U_NODES 200000
#define I_NODES 100000
#define N_NODES 300000
#define E_EDGES 1000000
#define DD 64
#define NB_SCAN 293   // ceil(300000/1024)
#define NBINS 256

// ---------------- scratch (static device globals; no allocation) ----------------
__device__ float g_w[E_EDGES];
__device__ float g_deg[N_NODES];
__device__ float g_dis[N_NODES];
__device__ int   g_cnt[N_NODES];
__device__ int   g_ptr[N_NODES + 1];
__device__ int   g_cur[N_NODES];
__device__ unsigned long long g_state[NB_SCAN + 1];  // [bid]=flag|value, [NB_SCAN]=ticket
__device__ int   g_adj[2 * E_EDGES];
__device__ float g_nrm[2 * E_EDGES];
__device__ int   g_hist[NBINS * NB_SCAN];   // [bin][bid]
__device__ int   g_bbase[NBINS * NB_SCAN];  // global base per (bin,bid)
__device__ int   g_order[N_NODES];          // degree-sorted node permutation
__device__ __align__(16) __half g_h0[(size_t)N_NODES * DD];   // x0 (fp16)
__device__ __align__(16) __half g_h1[(size_t)N_NODES * DD];   // x1 (fp16)
__device__ __align__(16) __half g_h2[(size_t)N_NODES * DD];   // x2 (fp16)

// ---------------- fp16 helpers ----------------
__device__ __forceinline__ uint2 pack4h(float4 f) {
    __half2 p0 = __floats2half2_rn(f.x, f.y);
    __half2 p1 = __floats2half2_rn(f.z, f.w);
    uint2 r;
    r.x = *reinterpret_cast<unsigned*>(&p0);
    r.y = *reinterpret_cast<unsigned*>(&p1);
    return r;
}
__device__ __forceinline__ float4 unpack4h(uint2 q) {
    __half2 p0 = *reinterpret_cast<__half2*>(&q.x);
    __half2 p1 = *reinterpret_cast<__half2*>(&q.y);
    float2 f0 = __half22float2(p0);
    float2 f1 = __half22float2(p1);
    return make_float4(f0.x, f0.y, f1.x, f1.y);
}

// ---------------- edge MLP + degree/count accumulation ----------------
__global__ void edge_mlp_kernel(const float* __restrict__ attr,
                                const int* __restrict__ src,
                                const int* __restrict__ dst,
                                const float* __restrict__ W1,
                                const float* __restrict__ b1,
                                const float* __restrict__ W2,
                                const float* __restrict__ b2) {
    __shared__ float sW1[8 * 32];
    __shared__ float sb1[32];
    __shared__ float sW2[32];
    __shared__ float sb2;
    int t = threadIdx.x;
    if (t < 256) sW1[t] = W1[t];
    if (t < 32) { sb1[t] = b1[t]; sW2[t] = W2[t]; }
    if (t == 0) sb2 = b2[0];
    __syncthreads();

    int e = blockIdx.x * blockDim.x + t;
    if (e >= E_EDGES) return;

    const float4* ap = (const float4*)(attr + (size_t)e * 8);
    float4 a0 = ap[0], a1 = ap[1];
    float a[8] = {a0.x, a0.y, a0.z, a0.w, a1.x, a1.y, a1.z, a1.w};

    float z = sb2;
#pragma unroll
    for (int j = 0; j < 32; j++) {
        float h = sb1[j];
#pragma unroll
        for (int k = 0; k < 8; k++) h = fmaf(a[k], sW1[k * 32 + j], h);
        z = fmaf(fmaxf(h, 0.0f), sW2[j], z);
    }
    float w = 1.0f / (1.0f + __expf(-z));
    w = fmaxf(w, 1e-6f);
    g_w[e] = w;

    int s = src[e];
    int d = dst[e] + U_NODES;
    atomicAdd(&g_deg[s], w);
    atomicAdd(&g_deg[d], w);
    atomicAdd(&g_cnt[s], 1);
    atomicAdd(&g_cnt[d], 1);
}

// ---------------- single-pass scan (decoupled lookback) + dis fused ----------------
__global__ void scan_fused_kernel() {
    __shared__ int ws[32];
    __shared__ int sbid;
    __shared__ int sexcl;
    int t = threadIdx.x;

    if (t == 0)
        sbid = (int)atomicAdd(&g_state[NB_SCAN], 1ULL);
    __syncthreads();
    int bid = sbid;

    int i = bid * 1024 + t;
    int v = 0;
    if (i < N_NODES) {
        v = g_cnt[i];
        g_dis[i] = rsqrtf(g_deg[i] + 1.0f);
    }

    int x = v;
#pragma unroll
    for (int o = 1; o < 32; o <<= 1) {
        int tmp = __shfl_up_sync(0xffffffffu, x, o);
        if ((t & 31) >= o) x += tmp;
    }
    if ((t & 31) == 31) ws[t >> 5] = x;
    __syncthreads();
    if (t < 32) {
        int s = ws[t];
#pragma unroll
        for (int o = 1; o < 32; o <<= 1) {
            int tmp = __shfl_up_sync(0xffffffffu, s, o);
            if (t >= o) s += tmp;
        }
        ws[t] = s;
    }
    __syncthreads();
    int wp = (t >= 32) ? ws[(t >> 5) - 1] : 0;
    int incl = x + wp;
    int total = ws[31];

    if (t == 0)
        atomicExch(&g_state[bid], (1ULL << 62) | (unsigned)total);

    if (t < 32) {
        int excl = 0;
        if (bid > 0) {
            int j = bid - 1;
            while (true) {
                int idx = j - t;
                unsigned long long s = 0;
                if (idx >= 0)
                    s = *(volatile unsigned long long*)(g_state + idx);
                unsigned flag = (unsigned)(s >> 62);
                int val = (int)(unsigned)(s & 0xFFFFFFFFu);
                bool active = (idx >= 0);
                unsigned pm = __ballot_sync(0xffffffffu, active && flag == 2u);
                unsigned im = __ballot_sync(0xffffffffu, active && flag == 0u);
                if (pm) {
                    int p = __ffs(pm) - 1;
                    if (im & ((1u << p) - 1u)) continue;
                    int contrib = (t <= p) ? val : 0;
#pragma unroll
                    for (int o = 16; o; o >>= 1)
                        contrib += __shfl_xor_sync(0xffffffffu, contrib, o);
                    excl += contrib;
                    break;
                } else {
                    if (im) continue;
                    int contrib = (t <= j) ? val : 0;
#pragma unroll
                    for (int o = 16; o; o >>= 1)
                        contrib += __shfl_xor_sync(0xffffffffu, contrib, o);
                    excl += contrib;
                    j -= 32;
                    if (j < 0) break;
                }
            }
        }
        if (t == 0) {
            atomicExch(&g_state[bid], (2ULL << 62) | (unsigned)(excl + total));
            sexcl = excl;
            if (bid == NB_SCAN - 1) g_ptr[N_NODES] = excl + total;
        }
    }
    __syncthreads();

    int e = sexcl + incl - v;
    if (i < N_NODES) { g_ptr[i] = e; g_cur[i] = e; }
}

// ---------------- degree counting sort: phase 1 per-block histogram ----------------
__global__ void hist_kernel() {
    __shared__ int sh[NBINS];
    int t = threadIdx.x;
    if (t < NBINS) sh[t] = 0;
    __syncthreads();
    int i = blockIdx.x * 1024 + t;
    if (i < N_NODES) {
        int b = g_cnt[i];
        if (b > NBINS - 1) b = NBINS - 1;
        atomicAdd(&sh[b], 1);
    }
    __syncthreads();
    if (t < NBINS) g_hist[t * NB_SCAN + blockIdx.x] = sh[t];
}

// ---------------- phase 2: bin bases (1 block, 256 threads; thread b owns bin b) -----
__global__ void binscan_kernel() {
    __shared__ int ws[8];
    int b = threadIdx.x;
    int tot = 0;
    for (int k = 0; k < NB_SCAN; k++) tot += g_hist[b * NB_SCAN + k];
    // exclusive scan of 256 totals
    int x = tot;
#pragma unroll
    for (int o = 1; o < 32; o <<= 1) {
        int tmp = __shfl_up_sync(0xffffffffu, x, o);
        if ((b & 31) >= o) x += tmp;
    }
    if ((b & 31) == 31) ws[b >> 5] = x;
    __syncthreads();
    if (b < 8) {
        int s = ws[b];
#pragma unroll
        for (int o = 1; o < 8; o <<= 1) {
            int tmp = __shfl_up_sync(0x000000ffu, s, o);
            if (b >= o) s += tmp;
        }
        ws[b] = s;
    }
    __syncthreads();
    int wp = (b >= 32) ? ws[(b >> 5) - 1] : 0;
    int base = x + wp - tot;   // exclusive
    // per-(bin,block) running bases
    int run = base;
    for (int k = 0; k < NB_SCAN; k++) {
        g_bbase[b * NB_SCAN + k] = run;
        run += g_hist[b * NB_SCAN + k];
    }
}

// ---------------- phase 3: scatter node ids into degree-sorted order ----------------
__global__ void order_kernel() {
    __shared__ int sc[NBINS];
    int t = threadIdx.x;
    if (t < NBINS) sc[t] = 0;
    __syncthreads();
    int i = blockIdx.x * 1024 + t;
    if (i < N_NODES) {
        int b = g_cnt[i];
        if (b > NBINS - 1) b = NBINS - 1;
        int l = atomicAdd(&sc[b], 1);
        g_order[g_bbase[b * NB_SCAN + blockIdx.x] + l] = i;
    }
}

// ---------------- scatter edges into CSR (split arrays) ----------------
__global__ void scatter_kernel(const int* __restrict__ src,
                               const int* __restrict__ dst) {
    int e = blockIdx.x * blockDim.x + threadIdx.x;
    if (e >= E_EDGES) return;
    int s = src[e];
    int d = dst[e] + U_NODES;
    float nf = g_dis[s] * g_w[e] * g_dis[d];
    int p1 = atomicAdd(&g_cur[d], 1);
    g_adj[p1] = s;
    g_nrm[p1] = nf;
    int p2 = atomicAdd(&g_cur[s], 1);
    g_adj[p2] = d;
    g_nrm[p2] = nf;
}

// ---------------- user init: l2norm(user_w) -> h0 (fp16) ----------------
__global__ void user_init_kernel(const float* __restrict__ uw) {
    int gid = blockIdx.x * blockDim.x + threadIdx.x;
    int n = gid >> 4;
    if (n >= U_NODES) return;
    int lane = threadIdx.x & 15;
    float4 v = ((const float4*)uw)[(size_t)n * 16 + lane];
    float s = v.x * v.x + v.y * v.y + v.z * v.z + v.w * v.w;
#pragma unroll
    for (int o = 8; o; o >>= 1) s += __shfl_xor_sync(0xffffffffu, s, o);
    float inv = 1.0f / fmaxf(sqrtf(s), 1e-12f);
    float4 out = make_float4(v.x * inv, v.y * inv, v.z * inv, v.w * inv);
    ((uint2*)g_h0)[(size_t)n * 16 + lane] = pack4h(out);
}

// ---------------- item init: wmma fp16 tensor-core GEMM -> h0 (fp16) ----------------
#define SA_LD 136
#define SB_LD 72
#define SC_LD 68

__global__ void __launch_bounds__(128)
item_init_kernel(const float* __restrict__ audio,
                 const float* __restrict__ artw,
                 const float* __restrict__ albw,
                 const int* __restrict__ aid,
                 const int* __restrict__ alid,
                 const float* __restrict__ Wp,
                 const float* __restrict__ bp) {
    __shared__ __align__(32) char sraw[64 * SA_LD * 2 + 128 * SB_LD * 2];
    __half* sA = (__half*)sraw;
    __half* sB = (__half*)(sraw + 64 * SA_LD * 2);
    float*  sC = (float*)sraw;

    int t = threadIdx.x;
    int item0 = blockIdx.x * 64;

    for (int idx = t; idx < 64 * 32; idx += 128) {
        int row = idx >> 5;
        int c4  = idx & 31;
        int item = item0 + row;
        float4 v = make_float4(0.f, 0.f, 0.f, 0.f);
        if (item < I_NODES) {
            if (c4 < 16) {
                v = __ldg((const float4*)audio + (size_t)item * 16 + c4);
            } else {
                int a_id  = __ldg(aid + item);
                int al_id = __ldg(alid + item);
                float4 x1 = __ldg((const float4*)artw + (size_t)a_id * 16 + (c4 - 16));
                float4 x2 = __ldg((const float4*)albw + (size_t)al_id * 16 + (c4 - 16));
                v = make_float4(x1.x + x2.x, x1.y + x2.y, x1.z + x2.z, x1.w + x2.w);
            }
        }
        *(uint2*)(sA + row * SA_LD + c4 * 4) = pack4h(v);
    }
    for (int idx = t; idx < 128 * 16; idx += 128) {
        int row = idx >> 4;
        int c4  = idx & 15;
        float4 v = __ldg((const float4*)Wp + (size_t)row * 16 + c4);
        *(uint2*)(sB + row * SB_LD + c4 * 4) = pack4h(v);
    }
    __syncthreads();

    {
        int w = t >> 5;
        wmma::fragment<wmma::accumulator, 16, 16, 16, float> c[4];
#pragma unroll
        for (int n = 0; n < 4; n++) wmma::fill_fragment(c[n], 0.0f);
#pragma unroll
        for (int k = 0; k < 8; k++) {
            wmma::fragment<wmma::matrix_a, 16, 16, 16, __half, wmma::row_major> af;
            wmma::load_matrix_sync(af, sA + (w * 16) * SA_LD + k * 16, SA_LD);
#pragma unroll
            for (int n = 0; n < 4; n++) {
                wmma::fragment<wmma::matrix_b, 16, 16, 16, __half, wmma::row_major> bf;
                wmma::load_matrix_sync(bf, sB + (k * 16) * SB_LD + n * 16, SB_LD);
                wmma::mma_sync(c[n], af, bf, c[n]);
            }
        }
#pragma unroll
        for (int n = 0; n < 4; n++)
            wmma::store_matrix_sync(sC + (w * 16) * SC_LD + n * 16, c[n],
                                    SC_LD, wmma::mem_row_major);
    }
    __syncthreads();

    {
        int item_l = t >> 1;
        int halfi  = t & 1;
        int item = item0 + item_l;
        const float* rowp = sC + item_l * SC_LD + halfi * 32;
        float vals[32];
        float s = 0.f;
#pragma unroll
        for (int j = 0; j < 32; j++) {
            float v = rowp[j] + __ldg(bp + halfi * 32 + j);
            vals[j] = v;
            s = fmaf(v, v, s);
        }
        s += __shfl_xor_sync(0xffffffffu, s, 1);
        float inv = 1.0f / fmaxf(sqrtf(s), 1e-12f);
        if (item < I_NODES) {
            uint2* dst = (uint2*)g_h0 + (size_t)(U_NODES + item) * 16 + halfi * 8;
#pragma unroll
            for (int j = 0; j < 8; j++) {
                float4 o = make_float4(vals[4 * j] * inv, vals[4 * j + 1] * inv,
                                       vals[4 * j + 2] * inv, vals[4 * j + 3] * inv);
                dst[j] = pack4h(o);
            }
        }
    }
}

// ---------------- one LGConv layer (16 lanes/node, degree-ordered nodes) -------------
// MODE 0: h0 -> h1 ; MODE 1: h1 -> h2 ; MODE 2: h2 -> out = l2norm(sum/4)
template<int MODE>
__global__ void gather_kernel(float* __restrict__ outp) {
    const uint2* hin = (MODE == 0) ? (const uint2*)g_h0
                     : (MODE == 1) ? (const uint2*)g_h1
                                   : (const uint2*)g_h2;

    int gid = blockIdx.x * blockDim.x + threadIdx.x;
    int idx = gid >> 4;
    if (idx >= N_NODES) return;
    int n = __ldg(g_order + idx);   // degree-sorted: paired nodes have equal degree
    int lane = threadIdx.x & 15;

    float dv = g_dis[n];
    float sw = dv * dv;
    float4 self = unpack4h(__ldg(hin + (size_t)n * 16 + lane));
    float4 a = make_float4(self.x * sw, self.y * sw, self.z * sw, self.w * sw);
    float4 a2 = make_float4(0.f, 0.f, 0.f, 0.f);

    int e = g_ptr[n];
    int end = g_ptr[n + 1];
    for (; e + 4 <= end; e += 4) {
        int j0 = __ldg(g_adj + e + 0);
        int j1 = __ldg(g_adj + e + 1);
        int j2 = __ldg(g_adj + e + 2);
        int j3 = __ldg(g_adj + e + 3);
        float v0 = __ldg(g_nrm + e + 0);
        float v1 = __ldg(g_nrm + e + 1);
        float v2 = __ldg(g_nrm + e + 2);
        float v3 = __ldg(g_nrm + e + 3);
        float4 x0 = unpack4h(__ldg(hin + (size_t)j0 * 16 + lane));
        float4 x1 = unpack4h(__ldg(hin + (size_t)j1 * 16 + lane));
        float4 x2 = unpack4h(__ldg(hin + (size_t)j2 * 16 + lane));
        float4 x3 = unpack4h(__ldg(hin + (size_t)j3 * 16 + lane));
        a.x  = fmaf(v0, x0.x, a.x);  a.y  = fmaf(v0, x0.y, a.y);
        a.z  = fmaf(v0, x0.z, a.z);  a.w  = fmaf(v0, x0.w, a.w);
        a.x  = fmaf(v1, x1.x, a.x);  a.y  = fmaf(v1, x1.y, a.y);
        a.z  = fmaf(v1, x1.z, a.z);  a.w  = fmaf(v1, x1.w, a.w);
        a2.x = fmaf(v2, x2.x, a2.x); a2.y = fmaf(v2, x2.y, a2.y);
        a2.z = fmaf(v2, x2.z, a2.z); a2.w = fmaf(v2, x2.w, a2.w);
        a2.x = fmaf(v3, x3.x, a2.x); a2.y = fmaf(v3, x3.y, a2.y);
        a2.z = fmaf(v3, x3.z, a2.z); a2.w = fmaf(v3, x3.w, a2.w);
    }
    for (; e < end; e++) {
        int j0 = __ldg(g_adj + e);
        float v0 = __ldg(g_nrm + e);
        float4 x0 = unpack4h(__ldg(hin + (size_t)j0 * 16 + lane));
        a.x = fmaf(v0, x0.x, a.x); a.y = fmaf(v0, x0.y, a.y);
        a.z = fmaf(v0, x0.z, a.z); a.w = fmaf(v0, x0.w, a.w);
    }
    a.x += a2.x; a.y += a2.y; a.z += a2.z; a.w += a2.w;

    if (MODE == 0) {
        ((uint2*)g_h1)[(size_t)n * 16 + lane] = pack4h(a);
    } else if (MODE == 1) {
        ((uint2*)g_h2)[(size_t)n * 16 + lane] = pack4h(a);
    } else {
        float4 x0 = unpack4h(__ldg((const uint2*)g_h0 + (size_t)n * 16 + lane));
        float4 x1 = unpack4h(__ldg((const uint2*)g_h1 + (size_t)n * 16 + lane));
        float4 c;
        c.x = (x0.x + x1.x + self.x + a.x) * 0.25f;
        c.y = (x0.y + x1.y + self.y + a.y) * 0.25f;
        c.z = (x0.z + x1.z + self.z + a.z) * 0.25f;
        c.w = (x0.w + x1.w + self.w + a.w) * 0.25f;
        float s = c.x * c.x + c.y * c.y + c.z * c.z + c.w * c.w;
#pragma unroll
        for (int o = 8; o; o >>= 1) s += __shfl_xor_sync(0xffffffffu, s, o);
        float inv = 1.0f / fmaxf(sqrtf(s), 1e-12f);
        ((float4*)outp)[(size_t)n * 16 + lane] =
            make_float4(c.x * inv, c.y * inv, c.z * inv, c.w * inv);
    }
}

// ---------------- streams + events + symbol addrs, once at static-init ----------------
__global__ void warmup_kernel() {}

namespace {
struct SideStream {
    cudaStream_t s2 = 0, s3 = 0;
    cudaEvent_t evFork = 0, evJoinB = 0, evScan = 0, evJoinC = 0;
    void* p_cnt = nullptr;
    void* p_deg = nullptr;
    void* p_state = nullptr;
    bool ok = false;
    SideStream() {
        if (cudaStreamCreateWithFlags(&s2, cudaStreamNonBlocking) != cudaSuccess) return;
        if (cudaStreamCreateWithFlags(&s3, cudaStreamNonBlocking) != cudaSuccess) return;
        if (cudaEventCreateWithFlags(&evFork, cudaEventDisableTiming) != cudaSuccess) return;
        if (cudaEventCreateWithFlags(&evJoinB, cudaEventDisableTiming) != cudaSuccess) return;
        if (cudaEventCreateWithFlags(&evScan, cudaEventDisableTiming) != cudaSuccess) return;
        if (cudaEventCreateWithFlags(&evJoinC, cudaEventDisableTiming) != cudaSuccess) return;
        if (cudaGetSymbolAddress(&p_cnt, g_cnt) != cudaSuccess) return;
        if (cudaGetSymbolAddress(&p_deg, g_deg) != cudaSuccess) return;
        if (cudaGetSymbolAddress(&p_state, g_state) != cudaSuccess) return;
        warmup_kernel<<<1, 32>>>();
        warmup_kernel<<<1, 32, 0, s2>>>();
        warmup_kernel<<<1, 32, 0, s3>>>();
        if (cudaDeviceSynchronize() != cudaSuccess) return;
        ok = true;
    }
};
SideStream g_side;
}

extern "C" void kernel_launch(void* const* d_in, const int* in_sizes, int n_in,
                              void* d_out, int out_size) {
    const int*   edge_src   = (const int*)d_in[0];
    const int*   edge_dst   = (const int*)d_in[1];
    const float* edge_attr  = (const float*)d_in[2];
    const float* user_w     = (const float*)d_in[3];
    const float* artist_w   = (const float*)d_in[4];
    const float* album_w    = (const float*)d_in[5];
    const float* item_audio = (const float*)d_in[6];
    const int*   artist_ids = (const int*)d_in[7];
    const int*   album_ids  = (const int*)d_in[8];
    const float* Wp         = (const float*)d_in[9];
    const float* bp         = (const float*)d_in[10];
    const float* W1         = (const float*)d_in[11];
    const float* b1         = (const float*)d_in[12];
    const float* W2         = (const float*)d_in[13];
    const float* b2         = (const float*)d_in[14];
    float* out = (float*)d_out;

    const int TPB = 256;
    bool fork = g_side.ok;
    cudaStream_t sB = fork ? g_side.s2 : (cudaStream_t)0;
    cudaStream_t sC = fork ? g_side.s3 : (cudaStream_t)0;

    // zero cnt/deg + scan state/ticket via memset nodes
    cudaMemsetAsync(g_side.p_cnt, 0, (size_t)N_NODES * sizeof(int), 0);
    cudaMemsetAsync(g_side.p_deg, 0, (size_t)N_NODES * sizeof(float), 0);
    cudaMemsetAsync(g_side.p_state, 0, (size_t)(NB_SCAN + 1) * sizeof(unsigned long long), 0);

    if (fork) {
        cudaEventRecord(g_side.evFork, 0);
        cudaStreamWaitEvent(sB, g_side.evFork, 0);
    }

    // ---- chain B (side stream): node feature init ----
    user_init_kernel<<<(U_NODES * 16 + TPB - 1) / TPB, TPB, 0, sB>>>(user_w);
    item_init_kernel<<<(I_NODES + 63) / 64, 128, 0, sB>>>(item_audio, artist_w, album_w,
                                                          artist_ids, album_ids, Wp, bp);
    if (fork) cudaEventRecord(g_side.evJoinB, sB);

    // ---- chain A (main stream): graph build ----
    edge_mlp_kernel<<<(E_EDGES + TPB - 1) / TPB, TPB>>>(edge_attr, edge_src, edge_dst,
                                                        W1, b1, W2, b2);
    scan_fused_kernel<<<NB_SCAN, 1024>>>();   // dis + single-pass ptr/cur scan
    if (fork) {
        cudaEventRecord(g_side.evScan, 0);
        cudaStreamWaitEvent(sC, g_side.evScan, 0);
    }

    // ---- chain C (overlapped with scatter): degree counting sort -> g_order ----
    hist_kernel<<<NB_SCAN, 1024, 0, sC>>>();
    binscan_kernel<<<1, NBINS, 0, sC>>>();
    order_kernel<<<NB_SCAN, 1024, 0, sC>>>();
    if (fork) cudaEventRecord(g_side.evJoinC, sC);

    scatter_kernel<<<(E_EDGES + TPB - 1) / TPB, TPB>>>(edge_src, edge_dst);

    if (fork) {
        cudaStreamWaitEvent((cudaStream_t)0, g_side.evJoinC, 0);
        cudaStreamWaitEvent((cudaStream_t)0, g_side.evJoinB, 0);
    }

    // ---- 3 propagation layers (16 lanes/node, degree-ordered) ----
    int nblocks = (N_NODES * 16 + TPB - 1) / TPB;
    gather_kernel<0><<<nblocks, TPB>>>(nullptr);
    gather_kernel<1><<<nblocks, TPB>>>(nullptr);
    gather_kernel<2><<<nblocks, TPB>>>(out);
}

// round 17
// speedup vs baseline: 1.2115x; 1.2115x over previous
#include <cuda_runtime.h>
#include <cuda_fp16.h>
#include <mma.h>
#include <math.h>

using namespace nvcuda;

#define U_NODES 200000
#define I_NODES 100000
#define N_NODES 300000
#define E_EDGES 1000000
#define DD 64
#define NB_SCAN 293   // ceil(300000/1024)

// ---------------- scratch (static device globals; no allocation) ----------------
__device__ float g_w[E_EDGES];
__device__ float g_deg[N_NODES];
__device__ float g_dis[N_NODES];
__device__ int   g_cnt[N_NODES];
__device__ int   g_ptr[N_NODES + 1];
__device__ int   g_cur[N_NODES];
__device__ unsigned long long g_state[NB_SCAN + 1];  // [bid]=flag|value, [NB_SCAN]=ticket
__device__ int   g_adj[2 * E_EDGES];
__device__ float g_nrm[2 * E_EDGES];
__device__ __align__(16) __half g_h0[(size_t)N_NODES * DD];   // x0 (fp16)
__device__ __align__(16) __half g_h1[(size_t)N_NODES * DD];   // x1 (fp16)
__device__ __align__(16) __half g_h2[(size_t)N_NODES * DD];   // x2 (fp16)

// ---------------- fp16 helpers ----------------
__device__ __forceinline__ uint2 pack4h(float4 f) {
    __half2 p0 = __floats2half2_rn(f.x, f.y);
    __half2 p1 = __floats2half2_rn(f.z, f.w);
    uint2 r;
    r.x = *reinterpret_cast<unsigned*>(&p0);
    r.y = *reinterpret_cast<unsigned*>(&p1);
    return r;
}
__device__ __forceinline__ float4 unpack4h(uint2 q) {
    __half2 p0 = *reinterpret_cast<__half2*>(&q.x);
    __half2 p1 = *reinterpret_cast<__half2*>(&q.y);
    float2 f0 = __half22float2(p0);
    float2 f1 = __half22float2(p1);
    return make_float4(f0.x, f0.y, f1.x, f1.y);
}

// ---------------- edge MLP + degree/count accumulation ----------------
__global__ void edge_mlp_kernel(const float* __restrict__ attr,
                                const int* __restrict__ src,
                                const int* __restrict__ dst,
                                const float* __restrict__ W1,
                                const float* __restrict__ b1,
                                const float* __restrict__ W2,
                                const float* __restrict__ b2) {
    __shared__ float sW1[8 * 32];
    __shared__ float sb1[32];
    __shared__ float sW2[32];
    __shared__ float sb2;
    int t = threadIdx.x;
    if (t < 256) sW1[t] = W1[t];
    if (t < 32) { sb1[t] = b1[t]; sW2[t] = W2[t]; }
    if (t == 0) sb2 = b2[0];
    __syncthreads();

    int e = blockIdx.x * blockDim.x + t;
    if (e >= E_EDGES) return;

    const float4* ap = (const float4*)(attr + (size_t)e * 8);
    float4 a0 = ap[0], a1 = ap[1];
    float a[8] = {a0.x, a0.y, a0.z, a0.w, a1.x, a1.y, a1.z, a1.w};

    float z = sb2;
#pragma unroll
    for (int j = 0; j < 32; j++) {
        float h = sb1[j];
#pragma unroll
        for (int k = 0; k < 8; k++) h = fmaf(a[k], sW1[k * 32 + j], h);
        z = fmaf(fmaxf(h, 0.0f), sW2[j], z);
    }
    float w = 1.0f / (1.0f + __expf(-z));
    w = fmaxf(w, 1e-6f);
    g_w[e] = w;

    int s = src[e];
    int d = dst[e] + U_NODES;
    atomicAdd(&g_deg[s], w);
    atomicAdd(&g_deg[d], w);
    atomicAdd(&g_cnt[s], 1);
    atomicAdd(&g_cnt[d], 1);
}

// ---------------- single-pass scan (decoupled lookback) + dis fused ----------------
// flag in bits[63:62]: 0=invalid, 1=aggregate, 2=inclusive prefix. value in low 32 bits.
__global__ void scan_fused_kernel() {
    __shared__ int ws[32];
    __shared__ int sbid;
    __shared__ int sexcl;
    int t = threadIdx.x;

    if (t == 0)
        sbid = (int)atomicAdd(&g_state[NB_SCAN], 1ULL);
    __syncthreads();
    int bid = sbid;

    int i = bid * 1024 + t;
    int v = 0;
    if (i < N_NODES) {
        v = g_cnt[i];
        g_dis[i] = rsqrtf(g_deg[i] + 1.0f);
    }

    // block-wide inclusive scan of v
    int x = v;
#pragma unroll
    for (int o = 1; o < 32; o <<= 1) {
        int tmp = __shfl_up_sync(0xffffffffu, x, o);
        if ((t & 31) >= o) x += tmp;
    }
    if ((t & 31) == 31) ws[t >> 5] = x;
    __syncthreads();
    if (t < 32) {
        int s = ws[t];
#pragma unroll
        for (int o = 1; o < 32; o <<= 1) {
            int tmp = __shfl_up_sync(0xffffffffu, s, o);
            if (t >= o) s += tmp;
        }
        ws[t] = s;
    }
    __syncthreads();
    int wp = (t >= 32) ? ws[(t >> 5) - 1] : 0;
    int incl = x + wp;
    int total = ws[31];   // block total (padding lanes contribute 0)

    // publish aggregate
    if (t == 0)
        atomicExch(&g_state[bid], (1ULL << 62) | (unsigned)total);

    // warp 0: lookback
    if (t < 32) {
        int excl = 0;
        if (bid > 0) {
            int j = bid - 1;
            while (true) {
                int idx = j - t;
                unsigned long long s = 0;
                if (idx >= 0)
                    s = *(volatile unsigned long long*)(g_state + idx);
                unsigned flag = (unsigned)(s >> 62);
                int val = (int)(unsigned)(s & 0xFFFFFFFFu);
                bool active = (idx >= 0);
                unsigned pm = __ballot_sync(0xffffffffu, active && flag == 2u);
                unsigned im = __ballot_sync(0xffffffffu, active && flag == 0u);
                if (pm) {
                    int p = __ffs(pm) - 1;                 // nearest prefix lane
                    if (im & ((1u << p) - 1u)) continue;   // gap before prefix: retry
                    int contrib = (t <= p) ? val : 0;
#pragma unroll
                    for (int o = 16; o; o >>= 1)
                        contrib += __shfl_xor_sync(0xffffffffu, contrib, o);
                    excl += contrib;
                    break;
                } else {
                    if (im) continue;                      // not all ready: retry
                    int contrib = (t <= j) ? val : 0;      // only lanes with idx>=0
#pragma unroll
                    for (int o = 16; o; o >>= 1)
                        contrib += __shfl_xor_sync(0xffffffffu, contrib, o);
                    excl += contrib;
                    j -= 32;
                    if (j < 0) break;
                }
            }
        }
        if (t == 0) {
            atomicExch(&g_state[bid], (2ULL << 62) | (unsigned)(excl + total));
            sexcl = excl;
            if (bid == NB_SCAN - 1) g_ptr[N_NODES] = excl + total;
        }
    }
    __syncthreads();

    int e = sexcl + incl - v;
    if (i < N_NODES) { g_ptr[i] = e; g_cur[i] = e; }
}

// ---------------- scatter edges into CSR (split arrays) ----------------
__global__ void scatter_kernel(const int* __restrict__ src,
                               const int* __restrict__ dst) {
    int e = blockIdx.x * blockDim.x + threadIdx.x;
    if (e >= E_EDGES) return;
    int s = src[e];
    int d = dst[e] + U_NODES;
    float nf = g_dis[s] * g_w[e] * g_dis[d];
    int p1 = atomicAdd(&g_cur[d], 1);
    g_adj[p1] = s;
    g_nrm[p1] = nf;
    int p2 = atomicAdd(&g_cur[s], 1);
    g_adj[p2] = d;
    g_nrm[p2] = nf;
}

// ---------------- user init: l2norm(user_w) -> h0 (fp16) ----------------
__global__ void user_init_kernel(const float* __restrict__ uw) {
    int gid = blockIdx.x * blockDim.x + threadIdx.x;
    int n = gid >> 4;
    if (n >= U_NODES) return;
    int lane = threadIdx.x & 15;
    float4 v = ((const float4*)uw)[(size_t)n * 16 + lane];
    float s = v.x * v.x + v.y * v.y + v.z * v.z + v.w * v.w;
#pragma unroll
    for (int o = 8; o; o >>= 1) s += __shfl_xor_sync(0xffffffffu, s, o);
    float inv = 1.0f / fmaxf(sqrtf(s), 1e-12f);
    float4 out = make_float4(v.x * inv, v.y * inv, v.z * inv, v.w * inv);
    ((uint2*)g_h0)[(size_t)n * 16 + lane] = pack4h(out);
}

// ---------------- item init: wmma fp16 tensor-core GEMM -> h0 (fp16) ----------------
#define SA_LD 136   // halves per A row (128 + 8 pad)
#define SB_LD 72    // halves per B row (64 + 8 pad)
#define SC_LD 68    // floats per C row (64 + 4 pad); C row = 272B = A row

__global__ void __launch_bounds__(128)
item_init_kernel(const float* __restrict__ audio,
                 const float* __restrict__ artw,
                 const float* __restrict__ albw,
                 const int* __restrict__ aid,
                 const int* __restrict__ alid,
                 const float* __restrict__ Wp,
                 const float* __restrict__ bp) {
    __shared__ __align__(32) char sraw[64 * SA_LD * 2 + 128 * SB_LD * 2];
    __half* sA = (__half*)sraw;
    __half* sB = (__half*)(sraw + 64 * SA_LD * 2);
    float*  sC = (float*)sraw;    // aliases sA (same 272B row pitch)

    int t = threadIdx.x;
    int item0 = blockIdx.x * 64;

    // ---- stage A: [64 items][128 cols] fp32 -> fp16 (audio | artist+album) ----
    for (int idx = t; idx < 64 * 32; idx += 128) {
        int row = idx >> 5;
        int c4  = idx & 31;
        int item = item0 + row;
        float4 v = make_float4(0.f, 0.f, 0.f, 0.f);
        if (item < I_NODES) {
            if (c4 < 16) {
                v = __ldg((const float4*)audio + (size_t)item * 16 + c4);
            } else {
                int a_id  = __ldg(aid + item);
                int al_id = __ldg(alid + item);
                float4 x1 = __ldg((const float4*)artw + (size_t)a_id * 16 + (c4 - 16));
                float4 x2 = __ldg((const float4*)albw + (size_t)al_id * 16 + (c4 - 16));
                v = make_float4(x1.x + x2.x, x1.y + x2.y, x1.z + x2.z, x1.w + x2.w);
            }
        }
        *(uint2*)(sA + row * SA_LD + c4 * 4) = pack4h(v);
    }
    // ---- stage B: Wp [128 k][64 n] fp32 -> fp16 ----
    for (int idx = t; idx < 128 * 16; idx += 128) {
        int row = idx >> 4;
        int c4  = idx & 15;
        float4 v = __ldg((const float4*)Wp + (size_t)row * 16 + c4);
        *(uint2*)(sB + row * SB_LD + c4 * 4) = pack4h(v);
    }
    __syncthreads();

    // ---- tensor-core GEMM: warp w -> rows [w*16, w*16+16) x 64 cols ----
    {
        int w = t >> 5;
        wmma::fragment<wmma::accumulator, 16, 16, 16, float> c[4];
#pragma unroll
        for (int n = 0; n < 4; n++) wmma::fill_fragment(c[n], 0.0f);
#pragma unroll
        for (int k = 0; k < 8; k++) {
            wmma::fragment<wmma::matrix_a, 16, 16, 16, __half, wmma::row_major> af;
            wmma::load_matrix_sync(af, sA + (w * 16) * SA_LD + k * 16, SA_LD);
#pragma unroll
            for (int n = 0; n < 4; n++) {
                wmma::fragment<wmma::matrix_b, 16, 16, 16, __half, wmma::row_major> bf;
                wmma::load_matrix_sync(bf, sB + (k * 16) * SB_LD + n * 16, SB_LD);
                wmma::mma_sync(c[n], af, bf, c[n]);
            }
        }
        // store over own A rows (this warp is the only reader of those rows)
#pragma unroll
        for (int n = 0; n < 4; n++)
            wmma::store_matrix_sync(sC + (w * 16) * SC_LD + n * 16, c[n],
                                    SC_LD, wmma::mem_row_major);
    }
    __syncthreads();

    // ---- bias + l2norm + fp16 pack: 2 threads per item ----
    {
        int item_l = t >> 1;
        int halfi  = t & 1;
        int item = item0 + item_l;
        const float* rowp = sC + item_l * SC_LD + halfi * 32;
        float vals[32];
        float s = 0.f;
#pragma unroll
        for (int j = 0; j < 32; j++) {
            float v = rowp[j] + __ldg(bp + halfi * 32 + j);
            vals[j] = v;
            s = fmaf(v, v, s);
        }
        s += __shfl_xor_sync(0xffffffffu, s, 1);
        float inv = 1.0f / fmaxf(sqrtf(s), 1e-12f);
        if (item < I_NODES) {
            uint2* dst = (uint2*)g_h0 + (size_t)(U_NODES + item) * 16 + halfi * 8;
#pragma unroll
            for (int j = 0; j < 8; j++) {
                float4 o = make_float4(vals[4 * j] * inv, vals[4 * j + 1] * inv,
                                       vals[4 * j + 2] * inv, vals[4 * j + 3] * inv);
                dst[j] = pack4h(o);
            }
        }
    }
}

// ---------------- one LGConv layer (16 lanes/node, uint2 fp16 rows, unroll 4/1) -------
// MODE 0: h0 -> h1
// MODE 1: h1 -> h2
// MODE 2: h2 -> out = l2norm((x0 + x1 + x2 + x3)/4)
template<int MODE>
__global__ void gather_kernel(float* __restrict__ outp) {
    const uint2* hin = (MODE == 0) ? (const uint2*)g_h0
                     : (MODE == 1) ? (const uint2*)g_h1
                                   : (const uint2*)g_h2;

    int gid = blockIdx.x * blockDim.x + threadIdx.x;
    int n = gid >> 4;
    if (n >= N_NODES) return;
    int lane = threadIdx.x & 15;

    float dv = g_dis[n];
    float sw = dv * dv;
    float4 self = unpack4h(__ldg(hin + (size_t)n * 16 + lane));
    float4 a = make_float4(self.x * sw, self.y * sw, self.z * sw, self.w * sw);
    float4 a2 = make_float4(0.f, 0.f, 0.f, 0.f);

    int e = g_ptr[n];
    int end = g_ptr[n + 1];
    for (; e + 4 <= end; e += 4) {
        int j0 = __ldg(g_adj + e + 0);
        int j1 = __ldg(g_adj + e + 1);
        int j2 = __ldg(g_adj + e + 2);
        int j3 = __ldg(g_adj + e + 3);
        float v0 = __ldg(g_nrm + e + 0);
        float v1 = __ldg(g_nrm + e + 1);
        float v2 = __ldg(g_nrm + e + 2);
        float v3 = __ldg(g_nrm + e + 3);
        float4 x0 = unpack4h(__ldg(hin + (size_t)j0 * 16 + lane));
        float4 x1 = unpack4h(__ldg(hin + (size_t)j1 * 16 + lane));
        float4 x2 = unpack4h(__ldg(hin + (size_t)j2 * 16 + lane));
        float4 x3 = unpack4h(__ldg(hin + (size_t)j3 * 16 + lane));
        a.x  = fmaf(v0, x0.x, a.x);  a.y  = fmaf(v0, x0.y, a.y);
        a.z  = fmaf(v0, x0.z, a.z);  a.w  = fmaf(v0, x0.w, a.w);
        a.x  = fmaf(v1, x1.x, a.x);  a.y  = fmaf(v1, x1.y, a.y);
        a.z  = fmaf(v1, x1.z, a.z);  a.w  = fmaf(v1, x1.w, a.w);
        a2.x = fmaf(v2, x2.x, a2.x); a2.y = fmaf(v2, x2.y, a2.y);
        a2.z = fmaf(v2, x2.z, a2.z); a2.w = fmaf(v2, x2.w, a2.w);
        a2.x = fmaf(v3, x3.x, a2.x); a2.y = fmaf(v3, x3.y, a2.y);
        a2.z = fmaf(v3, x3.z, a2.z); a2.w = fmaf(v3, x3.w, a2.w);
    }
    for (; e < end; e++) {
        int j0 = __ldg(g_adj + e);
        float v0 = __ldg(g_nrm + e);
        float4 x0 = unpack4h(__ldg(hin + (size_t)j0 * 16 + lane));
        a.x = fmaf(v0, x0.x, a.x); a.y = fmaf(v0, x0.y, a.y);
        a.z = fmaf(v0, x0.z, a.z); a.w = fmaf(v0, x0.w, a.w);
    }
    a.x += a2.x; a.y += a2.y; a.z += a2.z; a.w += a2.w;

    if (MODE == 0) {
        ((uint2*)g_h1)[(size_t)n * 16 + lane] = pack4h(a);
    } else if (MODE == 1) {
        ((uint2*)g_h2)[(size_t)n * 16 + lane] = pack4h(a);
    } else {
        float4 x0 = unpack4h(__ldg((const uint2*)g_h0 + (size_t)n * 16 + lane));
        float4 x1 = unpack4h(__ldg((const uint2*)g_h1 + (size_t)n * 16 + lane));
        float4 c;
        c.x = (x0.x + x1.x + self.x + a.x) * 0.25f;
        c.y = (x0.y + x1.y + self.y + a.y) * 0.25f;
        c.z = (x0.z + x1.z + self.z + a.z) * 0.25f;
        c.w = (x0.w + x1.w + self.w + a.w) * 0.25f;
        float s = c.x * c.x + c.y * c.y + c.z * c.z + c.w * c.w;
#pragma unroll
        for (int o = 8; o; o >>= 1) s += __shfl_xor_sync(0xffffffffu, s, o);
        float inv = 1.0f / fmaxf(sqrtf(s), 1e-12f);
        ((float4*)outp)[(size_t)n * 16 + lane] =
            make_float4(c.x * inv, c.y * inv, c.z * inv, c.w * inv);
    }
}

// ---------------- side stream + events + symbol addrs, once at static-init ----------------
__global__ void warmup_kernel() {}

namespace {
struct SideStream {
    cudaStream_t s2 = 0;
    cudaEvent_t evFork = 0, evJoin = 0;
    void* p_cnt = nullptr;
    void* p_deg = nullptr;
    void* p_state = nullptr;
    bool ok = false;
    SideStream() {
        if (cudaStreamCreateWithFlags(&s2, cudaStreamNonBlocking) != cudaSuccess) return;
        if (cudaEventCreateWithFlags(&evFork, cudaEventDisableTiming) != cudaSuccess) return;
        if (cudaEventCreateWithFlags(&evJoin, cudaEventDisableTiming) != cudaSuccess) return;
        if (cudaGetSymbolAddress(&p_cnt, g_cnt) != cudaSuccess) return;
        if (cudaGetSymbolAddress(&p_deg, g_deg) != cudaSuccess) return;
        if (cudaGetSymbolAddress(&p_state, g_state) != cudaSuccess) return;
        warmup_kernel<<<1, 32>>>();
        warmup_kernel<<<1, 32, 0, s2>>>();
        if (cudaDeviceSynchronize() != cudaSuccess) return;
        ok = true;
    }
};
SideStream g_side;
}

extern "C" void kernel_launch(void* const* d_in, const int* in_sizes, int n_in,
                              void* d_out, int out_size) {
    const int*   edge_src   = (const int*)d_in[0];
    const int*   edge_dst   = (const int*)d_in[1];
    const float* edge_attr  = (const float*)d_in[2];
    const float* user_w     = (const float*)d_in[3];
    const float* artist_w   = (const float*)d_in[4];
    const float* album_w    = (const float*)d_in[5];
    const float* item_audio = (const float*)d_in[6];
    const int*   artist_ids = (const int*)d_in[7];
    const int*   album_ids  = (const int*)d_in[8];
    const float* Wp         = (const float*)d_in[9];
    const float* bp         = (const float*)d_in[10];
    const float* W1         = (const float*)d_in[11];
    const float* b1         = (const float*)d_in[12];
    const float* W2         = (const float*)d_in[13];
    const float* b2         = (const float*)d_in[14];
    float* out = (float*)d_out;

    const int TPB = 256;
    bool fork = g_side.ok;
    cudaStream_t sB = fork ? g_side.s2 : (cudaStream_t)0;

    // zero cnt/deg + scan state/ticket via memset nodes
    cudaMemsetAsync(g_side.p_cnt, 0, (size_t)N_NODES * sizeof(int), 0);
    cudaMemsetAsync(g_side.p_deg, 0, (size_t)N_NODES * sizeof(float), 0);
    cudaMemsetAsync(g_side.p_state, 0, (size_t)(NB_SCAN + 1) * sizeof(unsigned long long), 0);

    if (fork) {
        cudaEventRecord(g_side.evFork, 0);
        cudaStreamWaitEvent(sB, g_side.evFork, 0);
    }

    // ---- chain B (side stream): node feature init ----
    user_init_kernel<<<(U_NODES * 16 + TPB - 1) / TPB, TPB, 0, sB>>>(user_w);
    item_init_kernel<<<(I_NODES + 63) / 64, 128, 0, sB>>>(item_audio, artist_w, album_w,
                                                          artist_ids, album_ids, Wp, bp);
    if (fork) cudaEventRecord(g_side.evJoin, sB);

    // ---- chain A (main stream): graph build ----
    edge_mlp_kernel<<<(E_EDGES + TPB - 1) / TPB, TPB>>>(edge_attr, edge_src, edge_dst,
                                                        W1, b1, W2, b2);
    scan_fused_kernel<<<NB_SCAN, 1024>>>();   // dis + single-pass ptr/cur scan
    scatter_kernel<<<(E_EDGES + TPB - 1) / TPB, TPB>>>(edge_src, edge_dst);

    if (fork) cudaStreamWaitEvent((cudaStream_t)0, g_side.evJoin, 0);

    // ---- 3 propagation layers (16 lanes/node) ----
    int nblocks = (N_NODES * 16 + TPB - 1) / TPB;
    gather_kernel<0><<<nblocks, TPB>>>(nullptr);
    gather_kernel<1><<<nblocks, TPB>>>(nullptr);
    gather_kernel<2><<<nblocks, TPB>>>(out);
}